// round 16
// baseline (speedup 1.0000x reference)
#include <cuda_runtime.h>

// Problem geometry (fixed by the reference)
#define WIDTH   1000
#define HEIGHT  1000
#define PS      5
#define NT      10
#define PPR     (WIDTH / PS)          // 200 patches per patch-row
#define NPIX    (WIDTH * HEIGHT)      // 1,000,000

constexpr int PATCHES_PER_BLOCK = 25;
constexpr int COLS_PER_BLOCK    = PATCHES_PER_BLOCK * PS;   // 125
constexpr int SEGS_PER_ROWSTRIP = WIDTH / COLS_PER_BLOCK;   // 8
constexpr int THREADS           = 128;
constexpr int COEF_PER_PATCH    = 3 * NT * 2;               // 60 floats = 240 B
constexpr int COEF_VEC16        = PATCHES_PER_BLOCK * COEF_PER_PATCH / 4; // 375 x 16B

using ull = unsigned long long;

// Packed dual-FMA on the f32x2 pipe (ptxas never auto-fuses this).
__device__ __forceinline__ ull fma2(ull a, ull b, ull c) {
    ull d;
    asm("fma.rn.f32x2 %0, %1, %2, %3;" : "=l"(d) : "l"(a), "l"(b), "l"(c));
    return d;
}
__device__ __forceinline__ void unpack2(ull h, float& lo, float& hi) {
    asm("mov.b64 {%0, %1}, %2;" : "=f"(lo), "=f"(hi) : "l"(h));
}
__device__ __forceinline__ void cp_async16(void* smem_dst, const void* gmem_src) {
    unsigned saddr = (unsigned)__cvta_generic_to_shared(smem_dst);
    asm volatile("cp.async.cg.shared.global [%0], [%1], 16;" :: "r"(saddr), "l"(gmem_src));
}

__global__ __launch_bounds__(THREADS)
void ts_approx_kernel(const float* __restrict__ pix,     // [NPIX, 2]
                      const float* __restrict__ coef,    // [NPATCH, 3, NT, 2]
                      const float* __restrict__ bias,    // [NPATCH, 3]
                      float* __restrict__ out)           // [3, NPIX]
{
    __shared__ float s_coef[PATCHES_PER_BLOCK * COEF_PER_PATCH]; // 6000 B

    const int b      = blockIdx.x;
    const int pr     = b / SEGS_PER_ROWSTRIP;     // patch-row 0..199
    const int seg    = b % SEGS_PER_ROWSTRIP;     // 0..7
    const int patch0 = pr * PPR + seg * PATCHES_PER_BLOCK;

    const int c    = threadIdx.x;                 // column within strip (0..124 active)
    const int col  = seg * COLS_PER_BLOCK + c;
    const int row0 = pr * PS;
    const int n0   = row0 * WIDTH + col;

    // ── Issue the 5 pixel loads FIRST so their DRAM latency overlaps staging.
    const ull* __restrict__ pixq = reinterpret_cast<const ull*>(pix);
    ull xy[PS];
    if (c < COLS_PER_BLOCK) {
        #pragma unroll
        for (int r = 0; r < PS; r++)
            xy[r] = pixq[n0 + r * WIDTH];
    }

    // Bias pre-load for the fold pass: thread fi<75 owns (patch fi/3, channel fi%3).
    // LDG issued here so its latency hides under the cp.async wait below.
    float bfold = 0.0f;
    if (threadIdx.x < PATCHES_PER_BLOCK * 3)
        bfold = bias[patch0 * 3 + threadIdx.x];

    // ── Stage coefficients via cp.async (no reg roundtrip, overlaps with above).
    {
        const float4* gc = reinterpret_cast<const float4*>(coef + (size_t)patch0 * COEF_PER_PATCH);
        float4* sc = reinterpret_cast<float4*>(s_coef);
        #pragma unroll
        for (int i = threadIdx.x; i < COEF_VEC16; i += THREADS)
            cp_async16(sc + i, gc + i);
        asm volatile("cp.async.commit_group;\n cp.async.wait_group 0;" ::: "memory");
    }
    __syncthreads();

    // ── Fold bias into b0 (coefficient [ch][t=0][d=1]) in smem: the Horner
    //    chain then delivers hy+bias for free and the epilogue is hx+hy.
    if (threadIdx.x < PATCHES_PER_BLOCK * 3) {
        const int p  = threadIdx.x / 3;
        const int ch = threadIdx.x % 3;
        s_coef[p * COEF_PER_PATCH + ch * 20 + 1] += bfold;
    }
    __syncthreads();

    if (c >= COLS_PER_BLOCK) return;

    const int pl = c / PS;                        // local patch 0..24

    #pragma unroll
    for (int ch = 0; ch < 3; ch++) {
        // 10 coefficient pairs (a_t,b_t): 5 x 16B smem loads, lane stride 240B
        // across ~7 distinct patches per warp -> conflict-free.
        const ulonglong2* cfc =
            reinterpret_cast<const ulonglong2*>(s_coef) + pl * 15 + ch * 5;
        const ulonglong2 u0 = cfc[0];   // (c0, c1) ; c0 = (a0, b0+bias)
        const ulonglong2 u1 = cfc[1];   // (c2, c3)
        const ulonglong2 u2 = cfc[2];   // (c4, c5)
        const ulonglong2 u3 = cfc[3];   // (c6, c7)
        const ulonglong2 u4 = cfc[4];   // (c8, c9)

        // 5 independent packed Horner chains (one per row) -> ILP 5.
        #pragma unroll
        for (int r = 0; r < PS; r++) {
            ull h = u4.y;                  // (a9, b9)
            h = fma2(h, xy[r], u4.x);
            h = fma2(h, xy[r], u3.y);
            h = fma2(h, xy[r], u3.x);
            h = fma2(h, xy[r], u2.y);
            h = fma2(h, xy[r], u2.x);
            h = fma2(h, xy[r], u1.y);
            h = fma2(h, xy[r], u1.x);
            h = fma2(h, xy[r], u0.y);
            h = fma2(h, xy[r], u0.x);      // + (a0, b0+bias)
            float hx, hy;
            unpack2(h, hx, hy);
            out[(size_t)ch * NPIX + n0 + r * WIDTH] = hx + hy;
        }
    }
}

extern "C" void kernel_launch(void* const* d_in, const int* in_sizes, int n_in,
                              void* d_out, int out_size)
{
    const float* pix  = (const float*)d_in[0];   // [1e6, 2]
    const float* coef = (const float*)d_in[1];   // [40000, 3, 10, 2]
    const float* bias = (const float*)d_in[2];   // [40000, 3]
    float* out        = (float*)d_out;           // [3, 1e6]

    const int nblocks = (HEIGHT / PS) * SEGS_PER_ROWSTRIP;   // 200 * 8 = 1600
    ts_approx_kernel<<<nblocks, THREADS>>>(pix, coef, bias, out);
}